// round 14
// baseline (speedup 1.0000x reference)
#include <cuda_runtime.h>
#include <cuda_bf16.h>
#include <cuda_fp16.h>
#include <cstdint>

#define B_  2
#define C_  1024
#define E_  1024

// Scratch (device globals — no allocation allowed)
__device__ __half g_xf[B_ * C_ * E_];
__device__ __half g_Wf[4 * E_ * E_];      // Wq, Wk, Wv, Wo (fp16)
__device__ __half g_Qf[B_ * C_ * E_];
__device__ __half g_Kf[B_ * C_ * E_];
__device__ __half g_Vf[B_ * C_ * E_];
__device__ __half g_AOf[B_ * C_ * E_];

// ---------------- helpers ----------------
__device__ __forceinline__ uint32_t smem_u32(const void* p) {
    uint32_t a;
    asm("{ .reg .u64 t; cvta.to.shared.u64 t, %1; cvt.u32.u64 %0, t; }" : "=r"(a) : "l"(p));
    return a;
}
__device__ __forceinline__ void ldsm4(uint32_t* r, uint32_t addr) {
    asm volatile("ldmatrix.sync.aligned.m8n8.x4.shared.b16 {%0,%1,%2,%3}, [%4];"
                 : "=r"(r[0]), "=r"(r[1]), "=r"(r[2]), "=r"(r[3]) : "r"(addr));
}
__device__ __forceinline__ void ldsm4t(uint32_t* r, uint32_t addr) {
    asm volatile("ldmatrix.sync.aligned.m8n8.x4.trans.shared.b16 {%0,%1,%2,%3}, [%4];"
                 : "=r"(r[0]), "=r"(r[1]), "=r"(r[2]), "=r"(r[3]) : "r"(addr));
}
__device__ __forceinline__ void mma_f16(float* d, const uint32_t* a, uint32_t b0, uint32_t b1) {
    asm volatile("mma.sync.aligned.m16n8k16.row.col.f32.f16.f16.f32 "
                 "{%0,%1,%2,%3},{%4,%5,%6,%7},{%8,%9},{%0,%1,%2,%3};"
                 : "+f"(d[0]), "+f"(d[1]), "+f"(d[2]), "+f"(d[3])
                 : "r"(a[0]), "r"(a[1]), "r"(a[2]), "r"(a[3]), "r"(b0), "r"(b1));
}
__device__ __forceinline__ void cp16(uint32_t saddr, const void* g) {
    asm volatile("cp.async.cg.shared.global [%0], [%1], 16;" :: "r"(saddr), "l"(g));
}
__device__ __forceinline__ void cp_commit() {
    asm volatile("cp.async.commit_group;" ::: "memory");
}
__device__ __forceinline__ void cp_wait1() {
    asm volatile("cp.async.wait_group 1;" ::: "memory");
}
__device__ __forceinline__ void cp_wait0() {
    asm volatile("cp.async.wait_group 0;" ::: "memory");
}
__device__ __forceinline__ uint32_t f2h2(float lo, float hi) {
    uint32_t r;
    asm("cvt.rn.f16x2.f32 %0, %1, %2;" : "=r"(r) : "f"(hi), "f"(lo));
    return r;
}
__device__ __forceinline__ uint32_t ex2h2(uint32_t x) {
    uint32_t r;
    asm("ex2.approx.f16x2 %0, %1;" : "=r"(r) : "r"(x));
    return r;
}
__device__ __forceinline__ __half2 u2h(uint32_t x) {
    return reinterpret_cast<__half2&>(x);
}

// ---------------------------------------------------------------------------
// Prep: x and all 4 W matrices -> fp16.
// ---------------------------------------------------------------------------
__global__ void __launch_bounds__(256)
prep_kernel(const float4* __restrict__ x,  const float4* __restrict__ wq,
            const float4* __restrict__ wk, const float4* __restrict__ wv,
            const float4* __restrict__ wo)
{
    const int i = blockIdx.x * 256 + threadIdx.x;
    const float4* src; __half* dst; int off;
    if (i < 524288) { src = x; off = i; dst = g_xf; }
    else {
        const int r = i - 524288;
        const int w = r >> 18;
        off = r & 262143;
        src = (w == 0) ? wq : (w == 1) ? wk : (w == 2) ? wv : wo;
        dst = g_Wf + (size_t)w * 1048576;
    }
    const float4 v = src[off];
    *(uint2*)&dst[(size_t)off * 4] = make_uint2(f2h2(v.x, v.y), f2h2(v.z, v.w));
}

// ---------------------------------------------------------------------------
// Single-fp16 HMMA NT GEMM, templated on BN (CTA n-tile: 128 or 64).
// Tile 128 x BN, BK=32, 8 warps (32 x BN/2 each), 3-stage cp.async ring.
// ---------------------------------------------------------------------------
template <int BN, int OUTMODE>
__device__ __forceinline__ void gemm_f16_body(
    const __half* __restrict__ A, const __half* __restrict__ Bw,
    float* __restrict__ dstf, __half* __restrict__ dst16, float scale,
    int bm, int bn, uint32_t smb, int t)
{
    constexpr int WN   = BN / 2;          // warp n-cols (64 or 32)
    constexpr int NF   = WN / 8;          // n8 fragments per warp (8 or 4)
    constexpr int NLD  = WN / 16;         // B ldsm per ks (4 or 2)
    constexpr int BOFF = 10240;           // A tile bytes (128 x 80)
    constexpr int STG  = BOFF + BN * 80;  // stage bytes

    const int lane = t & 31, warp = t >> 5;
    const int wm = (warp >> 1) * 32, wn = (warp & 1) * WN;

    float acc[2][NF][4] = {};

    const uint32_t aoff = (uint32_t)((wm + (lane & 15)) * 80 + (lane >> 4) * 16);
    const uint32_t boff = (uint32_t)((wn + ((lane >> 4) & 1) * 8 + (lane & 7)) * 80 +
                                     ((lane >> 3) & 1) * 16);
    const int r0 = t >> 2,         c0 = t & 3;
    const int r1 = (t + 256) >> 2, c1 = (t + 256) & 3;

    #define GPREF(buf, kt) do {                                                  \
        const uint32_t sb_ = smb + (uint32_t)((buf) * STG);                       \
        const size_t gA0 = (size_t)(bm + r0) * 1024 + (kt) + c0 * 8;              \
        const size_t gA1 = (size_t)(bm + r1) * 1024 + (kt) + c1 * 8;              \
        cp16(sb_ + r0 * 80 + c0 * 16, A + gA0);                                   \
        cp16(sb_ + r1 * 80 + c1 * 16, A + gA1);                                   \
        const size_t gB0 = (size_t)(bn + r0) * 1024 + (kt) + c0 * 8;              \
        cp16(sb_ + BOFF + r0 * 80 + c0 * 16, Bw + gB0);                           \
        if (BN == 128) {                                                          \
            const size_t gB1 = (size_t)(bn + r1) * 1024 + (kt) + c1 * 8;          \
            cp16(sb_ + BOFF + r1 * 80 + c1 * 16, Bw + gB1);                       \
        }                                                                          \
        cp_commit();                                                               \
    } while (0)

    GPREF(0, 0);
    GPREF(1, 32);

    int cbuf = 0, pbuf = 2;
    for (int s = 0; s < 32; s++) {
        if (s == 31) cp_wait0(); else cp_wait1();
        __syncthreads();
        if (s + 2 < 32) {
            GPREF(pbuf, (s + 2) * 32);
            pbuf = (pbuf == 2) ? 0 : pbuf + 1;
        }

        const uint32_t sb = smb + (uint32_t)(cbuf * STG);
        cbuf = (cbuf == 2) ? 0 : cbuf + 1;
        #pragma unroll
        for (int ks = 0; ks < 2; ks++) {
            uint32_t a[2][4], b[NLD][4];
            #pragma unroll
            for (int i = 0; i < 2; i++)
                ldsm4(a[i], sb + aoff + (uint32_t)(i * 16 * 80 + ks * 32));
            #pragma unroll
            for (int jj = 0; jj < NLD; jj++)
                ldsm4(b[jj], sb + BOFF + boff + (uint32_t)(jj * 16 * 80 + ks * 32));
            #pragma unroll
            for (int i = 0; i < 2; i++)
                #pragma unroll
                for (int j = 0; j < NF; j++)
                    mma_f16(acc[i][j], a[i],
                            b[j >> 1][(j & 1) * 2], b[j >> 1][(j & 1) * 2 + 1]);
        }
    }
    #undef GPREF

    #pragma unroll
    for (int i = 0; i < 2; i++)
        #pragma unroll
        for (int j = 0; j < NF; j++) {
            const int n  = bn + wn + j * 8 + (lane & 3) * 2;
            const int m0 = bm + wm + i * 16 + (lane >> 2);
            #pragma unroll
            for (int hrow = 0; hrow < 2; hrow++) {
                const int m = m0 + hrow * 8;
                const float v0 = acc[i][j][hrow * 2 + 0];
                const float v1 = acc[i][j][hrow * 2 + 1];
                if (OUTMODE == 0) {
                    *(float2*)&dstf[(size_t)m * 1024 + n] = make_float2(v0, v1);
                } else {
                    const int b = m >> 10, c = m & 1023, hd = n >> 4, h = n & 15;
                    const size_t idx = (((size_t)(b * 64 + hd)) << 14) + (size_t)c * 16 + h;
                    *(uint32_t*)(dst16 + idx) = f2h2(v0 * scale, v1 * scale);
                }
            }
        }
}

#define QKV_STG   (10240 + 128 * 80)
#define QKV_SMEM  (3 * QKV_STG)
#define O_STG     (10240 + 64 * 80)
#define O_SMEM    (3 * O_STG)

__global__ void __launch_bounds__(256, 2)
gemm_qkv_k()
{
    extern __shared__ char sm[];
    const uint32_t smb = smem_u32(sm);
    const int z = blockIdx.z;
    __half* dst = (z == 0) ? g_Qf : (z == 1) ? g_Kf : g_Vf;
    const float scale = (z == 0) ? 0.25f * 1.4426950408889634f : 1.0f;
    gemm_f16_body<128, 1>(g_xf, g_Wf + (size_t)z * 1048576, nullptr, dst, scale,
                          blockIdx.y * 128, blockIdx.x * 128, smb, threadIdx.x);
}

__global__ void __launch_bounds__(256, 3)
gemm_o_k(float* __restrict__ out)
{
    extern __shared__ char sm[];
    const uint32_t smb = smem_u32(sm);
    gemm_f16_body<64, 0>(g_AOf, g_Wf + 3u * 1048576, out, nullptr, 1.0f,
                         blockIdx.y * 128, blockIdx.x * 64, smb, threadIdx.x);
}

// ---------------------------------------------------------------------------
// fp16 HMMA flash attention (unchanged from R13): 32 q-rows/warp, 3-stage KV.
// ---------------------------------------------------------------------------
#define KV_STAGE 12288
#define Q_SMEM   12288
#define ATT_SMEM (Q_SMEM + 3 * KV_STAGE)

__global__ void __launch_bounds__(256, 2)
attn_mma_k()
{
    extern __shared__ char sm[];
    const uint32_t smq = smem_u32(sm);
    const uint32_t kvb = smq + Q_SMEM;

    const int t    = threadIdx.x;
    const int lane = t & 31, w = t >> 5;
    const int bh   = blockIdx.y;
    const int qt   = blockIdx.x * 256;

    const size_t gb = (size_t)bh << 14;

    {
        const int i0 = t, i1 = t + 256;
        const int r0 = i0 >> 1, h0 = i0 & 1;
        const int r1 = i1 >> 1, h1 = i1 & 1;
        *(uint4*)(sm + r0 * 48 + h0 * 16) =
            *(const uint4*)(g_Qf + gb + (size_t)(qt + r0) * 16 + h0 * 8);
        *(uint4*)(sm + r1 * 48 + h1 * 16) =
            *(const uint4*)(g_Qf + gb + (size_t)(qt + r1) * 16 + h1 * 8);
    }
    __syncthreads();

    uint32_t qf[2][4];
    #pragma unroll
    for (int qi = 0; qi < 2; qi++)
        ldsm4(qf[qi], smq + (uint32_t)((32 * w + qi * 16 + (lane & 15)) * 48 +
                                       (lane >> 4) * 16));

    float O0[2][4] = {}, O1[2][4] = {};
    float la[2] = {}, lb[2] = {};

    const int pr = t >> 1, ph2 = t & 1;

    #define KV_PREFETCH(buf, kt) do {                                            \
        const uint32_t sb_ = kvb + (uint32_t)((buf) * KV_STAGE);                  \
        const size_t go_ = gb + (size_t)((kt) + pr) * 16 + ph2 * 8;               \
        const uint32_t so_ = (uint32_t)(pr * 48 + ph2 * 16);                      \
        cp16(sb_ + so_,        g_Kf + go_);                                       \
        cp16(sb_ + 6144 + so_, g_Vf + go_);                                       \
        cp_commit();                                                               \
    } while (0)

    KV_PREFETCH(0, 0);
    KV_PREFETCH(1, 128);

    int cbuf = 0, pbuf = 2;
    for (int s = 0; s < 8; s++) {
        if (s == 7) cp_wait0(); else cp_wait1();
        __syncthreads();
        if (s + 2 < 8) {
            KV_PREFETCH(pbuf, (s + 2) * 128);
            pbuf = (pbuf == 2) ? 0 : pbuf + 1;
        }

        const uint32_t sb = kvb + (uint32_t)(cbuf * KV_STAGE);
        cbuf = (cbuf == 2) ? 0 : cbuf + 1;
        const uint32_t lrow = (uint32_t)((lane & 15) * 48 + (lane >> 4) * 16);

        #pragma unroll
        for (int q4 = 0; q4 < 4; q4++) {
            float S[2][2][2][4];
            #pragma unroll
            for (int a = 0; a < 2; a++)
                #pragma unroll
                for (int b = 0; b < 2; b++)
                    #pragma unroll
                    for (int c = 0; c < 2; c++)
                        #pragma unroll
                        for (int d = 0; d < 4; d++) S[a][b][c][d] = 0.0f;

            #pragma unroll
            for (int kc = 0; kc < 2; kc++) {
                uint32_t kh[4];
                ldsm4(kh, sb + (uint32_t)((q4 * 2 + kc) * 16 * 48) + lrow);
                #pragma unroll
                for (int qi = 0; qi < 2; qi++) {
                    mma_f16(S[kc][qi][0], qf[qi], kh[0], kh[2]);
                    mma_f16(S[kc][qi][1], qf[qi], kh[1], kh[3]);
                }
            }

            #pragma unroll
            for (int kc = 0; kc < 2; kc++) {
                uint32_t pa[2][4];
                #pragma unroll
                for (int qi = 0; qi < 2; qi++) {
                    pa[qi][0] = ex2h2(f2h2(S[kc][qi][0][0], S[kc][qi][0][1]));
                    pa[qi][1] = ex2h2(f2h2(S[kc][qi][0][2], S[kc][qi][0][3]));
                    pa[qi][2] = ex2h2(f2h2(S[kc][qi][1][0], S[kc][qi][1][1]));
                    pa[qi][3] = ex2h2(f2h2(S[kc][qi][1][2], S[kc][qi][1][3]));
                    const float2 fa = __half22float2(__hadd2(u2h(pa[qi][0]), u2h(pa[qi][2])));
                    const float2 fb = __half22float2(__hadd2(u2h(pa[qi][1]), u2h(pa[qi][3])));
                    la[qi] += fa.x + fa.y;
                    lb[qi] += fb.x + fb.y;
                }
                uint32_t vh[4];
                ldsm4t(vh, sb + 6144 + (uint32_t)((q4 * 2 + kc) * 16 * 48) + lrow);
                #pragma unroll
                for (int qi = 0; qi < 2; qi++) {
                    mma_f16(O0[qi], pa[qi], vh[0], vh[1]);
                    mma_f16(O1[qi], pa[qi], vh[2], vh[3]);
                }
            }
        }
    }
    #undef KV_PREFETCH

    const int g = lane >> 2, tq = lane & 3;
    const int b = bh >> 6, hd = bh & 63;
    #pragma unroll
    for (int qi = 0; qi < 2; qi++) {
        float A = la[qi], Bv = lb[qi];
        A  += __shfl_xor_sync(0xFFFFFFFF, A, 1);
        A  += __shfl_xor_sync(0xFFFFFFFF, A, 2);
        Bv += __shfl_xor_sync(0xFFFFFFFF, Bv, 1);
        Bv += __shfl_xor_sync(0xFFFFFFFF, Bv, 2);
        const float ia = 1.0f / A, ib = 1.0f / Bv;

        const int ca = qt + 32 * w + qi * 16 + g, cb = ca + 8;
        const size_t oa = ((size_t)(b * 1024 + ca)) * 1024 + hd * 16 + 2 * tq;
        const size_t ob = ((size_t)(b * 1024 + cb)) * 1024 + hd * 16 + 2 * tq;

        *(uint32_t*)(g_AOf + oa)     = f2h2(O0[qi][0] * ia, O0[qi][1] * ia);
        *(uint32_t*)(g_AOf + oa + 8) = f2h2(O1[qi][0] * ia, O1[qi][1] * ia);
        *(uint32_t*)(g_AOf + ob)     = f2h2(O0[qi][2] * ib, O0[qi][3] * ib);
        *(uint32_t*)(g_AOf + ob + 8) = f2h2(O1[qi][2] * ib, O1[qi][3] * ib);
    }
}

// ---------------------------------------------------------------------------
extern "C" void kernel_launch(void* const* d_in, const int* in_sizes, int n_in,
                              void* d_out, int out_size)
{
    const float* x  = (const float*)d_in[0];
    const float* Wq = (const float*)d_in[1];
    const float* Wk = (const float*)d_in[2];
    const float* Wv = (const float*)d_in[3];
    const float* Wo = (const float*)d_in[4];
    float* out = (float*)d_out;

    cudaFuncSetAttribute(gemm_qkv_k, cudaFuncAttributeMaxDynamicSharedMemorySize, QKV_SMEM);
    cudaFuncSetAttribute(gemm_o_k,   cudaFuncAttributeMaxDynamicSharedMemorySize, O_SMEM);
    cudaFuncSetAttribute(attn_mma_k, cudaFuncAttributeMaxDynamicSharedMemorySize, ATT_SMEM);
    cudaFuncSetAttribute(gemm_qkv_k, cudaFuncAttributePreferredSharedMemoryCarveout, 100);
    cudaFuncSetAttribute(gemm_o_k,   cudaFuncAttributePreferredSharedMemoryCarveout, 100);
    cudaFuncSetAttribute(attn_mma_k, cudaFuncAttributePreferredSharedMemoryCarveout, 100);

    prep_kernel<<<6144, 256>>>((const float4*)x, (const float4*)Wq,
                               (const float4*)Wk, (const float4*)Wv,
                               (const float4*)Wo);

    gemm_qkv_k<<<dim3(8, 16, 3), 256, QKV_SMEM>>>();

    attn_mma_k<<<dim3(4, 128), 256, ATT_SMEM>>>();

    gemm_o_k<<<dim3(16, 16), 256, O_SMEM>>>(out);
}

// round 15
// speedup vs baseline: 1.0801x; 1.0801x over previous
#include <cuda_runtime.h>
#include <cuda_bf16.h>
#include <cuda_fp16.h>
#include <cstdint>

#define B_  2
#define C_  1024
#define E_  1024

// Scratch (device globals — no allocation allowed)
__device__ __half g_xf[B_ * C_ * E_];
__device__ __half g_Wf[4 * E_ * E_];      // Wq, Wk, Wv, Wo (fp16)
__device__ __half g_Qf[B_ * C_ * E_];
__device__ __half g_Kf[B_ * C_ * E_];
__device__ __half g_Vf[B_ * C_ * E_];
__device__ __half g_AOf[B_ * C_ * E_];

// ---------------- helpers ----------------
__device__ __forceinline__ uint32_t smem_u32(const void* p) {
    uint32_t a;
    asm("{ .reg .u64 t; cvta.to.shared.u64 t, %1; cvt.u32.u64 %0, t; }" : "=r"(a) : "l"(p));
    return a;
}
__device__ __forceinline__ void ldsm4(uint32_t* r, uint32_t addr) {
    asm volatile("ldmatrix.sync.aligned.m8n8.x4.shared.b16 {%0,%1,%2,%3}, [%4];"
                 : "=r"(r[0]), "=r"(r[1]), "=r"(r[2]), "=r"(r[3]) : "r"(addr));
}
__device__ __forceinline__ void ldsm4t(uint32_t* r, uint32_t addr) {
    asm volatile("ldmatrix.sync.aligned.m8n8.x4.trans.shared.b16 {%0,%1,%2,%3}, [%4];"
                 : "=r"(r[0]), "=r"(r[1]), "=r"(r[2]), "=r"(r[3]) : "r"(addr));
}
__device__ __forceinline__ void mma_f16(float* d, const uint32_t* a, uint32_t b0, uint32_t b1) {
    asm volatile("mma.sync.aligned.m16n8k16.row.col.f32.f16.f16.f32 "
                 "{%0,%1,%2,%3},{%4,%5,%6,%7},{%8,%9},{%0,%1,%2,%3};"
                 : "+f"(d[0]), "+f"(d[1]), "+f"(d[2]), "+f"(d[3])
                 : "r"(a[0]), "r"(a[1]), "r"(a[2]), "r"(a[3]), "r"(b0), "r"(b1));
}
__device__ __forceinline__ void cp16(uint32_t saddr, const void* g) {
    asm volatile("cp.async.cg.shared.global [%0], [%1], 16;" :: "r"(saddr), "l"(g));
}
__device__ __forceinline__ void cp_commit() {
    asm volatile("cp.async.commit_group;" ::: "memory");
}
__device__ __forceinline__ void cp_wait1() {
    asm volatile("cp.async.wait_group 1;" ::: "memory");
}
__device__ __forceinline__ void cp_wait0() {
    asm volatile("cp.async.wait_group 0;" ::: "memory");
}
__device__ __forceinline__ uint32_t f2h2(float lo, float hi) {
    uint32_t r;
    asm("cvt.rn.f16x2.f32 %0, %1, %2;" : "=r"(r) : "f"(hi), "f"(lo));
    return r;
}
__device__ __forceinline__ uint32_t ex2h2(uint32_t x) {
    uint32_t r;
    asm("ex2.approx.f16x2 %0, %1;" : "=r"(r) : "r"(x));
    return r;
}
__device__ __forceinline__ __half2 u2h(uint32_t x) {
    return reinterpret_cast<__half2&>(x);
}

// ---------------------------------------------------------------------------
// Prep: x and all 4 W matrices -> fp16.
// ---------------------------------------------------------------------------
__global__ void __launch_bounds__(256)
prep_kernel(const float4* __restrict__ x,  const float4* __restrict__ wq,
            const float4* __restrict__ wk, const float4* __restrict__ wv,
            const float4* __restrict__ wo)
{
    const int i = blockIdx.x * 256 + threadIdx.x;
    const float4* src; __half* dst; int off;
    if (i < 524288) { src = x; off = i; dst = g_xf; }
    else {
        const int r = i - 524288;
        const int w = r >> 18;
        off = r & 262143;
        src = (w == 0) ? wq : (w == 1) ? wk : (w == 2) ? wv : wo;
        dst = g_Wf + (size_t)w * 1048576;
    }
    const float4 v = src[off];
    *(uint2*)&dst[(size_t)off * 4] = make_uint2(f2h2(v.x, v.y), f2h2(v.z, v.w));
}

// ---------------------------------------------------------------------------
// Single-fp16 HMMA NT GEMM, BK=64, 3-stage ring, templated on BN (128/64).
// Tile 128 x BN, 8 warps (32 x BN/2 each). Row stride 144B in smem.
// ---------------------------------------------------------------------------
#define ROWB 144
#define A_TILE (128 * ROWB)                 // 18432

template <int BN, int OUTMODE>
__device__ __forceinline__ void gemm_f16_body(
    const __half* __restrict__ A, const __half* __restrict__ Bw,
    float* __restrict__ dstf, __half* __restrict__ dst16, float scale,
    int bm, int bn, uint32_t smb, int t)
{
    constexpr int WN   = BN / 2;
    constexpr int NF   = WN / 8;
    constexpr int NLD  = WN / 16;
    constexpr int STG  = A_TILE + BN * ROWB;
    constexpr int NBCH = (BN * 8) / 256;     // B cp16 per thread (4 or 2)

    const int lane = t & 31, warp = t >> 5;
    const int wm = (warp >> 1) * 32, wn = (warp & 1) * WN;

    float acc[2][NF][4] = {};

    const uint32_t aoff = (uint32_t)((wm + (lane & 15)) * ROWB + (lane >> 4) * 16);
    const uint32_t boff = (uint32_t)((wn + ((lane >> 4) & 1) * 8 + (lane & 7)) * ROWB +
                                     ((lane >> 3) & 1) * 16);

    #define GPREF(buf, kt) do {                                                  \
        const uint32_t sb_ = smb + (uint32_t)((buf) * STG);                       \
        _Pragma("unroll")                                                          \
        for (int j = 0; j < 4; j++) {                                              \
            const int idx = t + j * 256;                                          \
            const int row = idx >> 3, col = idx & 7;                              \
            cp16(sb_ + row * ROWB + col * 16,                                     \
                 A + (size_t)(bm + row) * 1024 + (kt) + col * 8);                 \
        }                                                                          \
        _Pragma("unroll")                                                          \
        for (int j = 0; j < NBCH; j++) {                                           \
            const int idx = t + j * 256;                                          \
            const int row = idx >> 3, col = idx & 7;                              \
            cp16(sb_ + A_TILE + row * ROWB + col * 16,                            \
                 Bw + (size_t)(bn + row) * 1024 + (kt) + col * 8);                \
        }                                                                          \
        cp_commit();                                                               \
    } while (0)

    GPREF(0, 0);
    GPREF(1, 64);

    for (int s = 0; s < 16; s++) {
        if (s == 15) cp_wait0(); else cp_wait1();
        __syncthreads();
        if (s + 2 < 16) GPREF((s + 2) % 3, (s + 2) * 64);

        const uint32_t sb = smb + (uint32_t)((s % 3) * STG);
        #pragma unroll
        for (int ks = 0; ks < 4; ks++) {
            uint32_t a[2][4], b[NLD][4];
            #pragma unroll
            for (int i = 0; i < 2; i++)
                ldsm4(a[i], sb + aoff + (uint32_t)(i * 16 * ROWB + ks * 32));
            #pragma unroll
            for (int jj = 0; jj < NLD; jj++)
                ldsm4(b[jj], sb + A_TILE + boff + (uint32_t)(jj * 16 * ROWB + ks * 32));
            #pragma unroll
            for (int i = 0; i < 2; i++)
                #pragma unroll
                for (int j = 0; j < NF; j++)
                    mma_f16(acc[i][j], a[i],
                            b[j >> 1][(j & 1) * 2], b[j >> 1][(j & 1) * 2 + 1]);
        }
    }
    #undef GPREF

    #pragma unroll
    for (int i = 0; i < 2; i++)
        #pragma unroll
        for (int j = 0; j < NF; j++) {
            const int n  = bn + wn + j * 8 + (lane & 3) * 2;
            const int m0 = bm + wm + i * 16 + (lane >> 2);
            #pragma unroll
            for (int hrow = 0; hrow < 2; hrow++) {
                const int m = m0 + hrow * 8;
                const float v0 = acc[i][j][hrow * 2 + 0];
                const float v1 = acc[i][j][hrow * 2 + 1];
                if (OUTMODE == 0) {
                    *(float2*)&dstf[(size_t)m * 1024 + n] = make_float2(v0, v1);
                } else {
                    const int b = m >> 10, c = m & 1023, hd = n >> 4, h = n & 15;
                    const size_t idx = (((size_t)(b * 64 + hd)) << 14) + (size_t)c * 16 + h;
                    *(uint32_t*)(dst16 + idx) = f2h2(v0 * scale, v1 * scale);
                }
            }
        }
}

#define QKV_SMEM (3 * (A_TILE + 128 * ROWB))   // 110592
#define O_SMEM   (3 * (A_TILE + 64 * ROWB))    // 82944

__global__ void __launch_bounds__(256, 2)
gemm_qkv_k()
{
    extern __shared__ char sm[];
    const uint32_t smb = smem_u32(sm);
    const int z = blockIdx.z;
    __half* dst = (z == 0) ? g_Qf : (z == 1) ? g_Kf : g_Vf;
    const float scale = (z == 0) ? 0.25f * 1.4426950408889634f : 1.0f;
    gemm_f16_body<128, 1>(g_xf, g_Wf + (size_t)z * 1048576, nullptr, dst, scale,
                          blockIdx.y * 128, blockIdx.x * 128, smb, threadIdx.x);
}

__global__ void __launch_bounds__(256, 2)
gemm_o_k(float* __restrict__ out)
{
    extern __shared__ char sm[];
    const uint32_t smb = smem_u32(sm);
    gemm_f16_body<64, 0>(g_AOf, g_Wf + 3u * 1048576, out, nullptr, 1.0f,
                         blockIdx.y * 128, blockIdx.x * 64, smb, threadIdx.x);
}

// ---------------------------------------------------------------------------
// fp16 HMMA flash attention (unchanged from R13): 32 q-rows/warp, 3-stage KV.
// ---------------------------------------------------------------------------
#define KV_STAGE 12288
#define Q_SMEM   12288
#define ATT_SMEM (Q_SMEM + 3 * KV_STAGE)

__global__ void __launch_bounds__(256, 2)
attn_mma_k()
{
    extern __shared__ char sm[];
    const uint32_t smq = smem_u32(sm);
    const uint32_t kvb = smq + Q_SMEM;

    const int t    = threadIdx.x;
    const int lane = t & 31, w = t >> 5;
    const int bh   = blockIdx.y;
    const int qt   = blockIdx.x * 256;

    const size_t gb = (size_t)bh << 14;

    {
        const int i0 = t, i1 = t + 256;
        const int r0 = i0 >> 1, h0 = i0 & 1;
        const int r1 = i1 >> 1, h1 = i1 & 1;
        *(uint4*)(sm + r0 * 48 + h0 * 16) =
            *(const uint4*)(g_Qf + gb + (size_t)(qt + r0) * 16 + h0 * 8);
        *(uint4*)(sm + r1 * 48 + h1 * 16) =
            *(const uint4*)(g_Qf + gb + (size_t)(qt + r1) * 16 + h1 * 8);
    }
    __syncthreads();

    uint32_t qf[2][4];
    #pragma unroll
    for (int qi = 0; qi < 2; qi++)
        ldsm4(qf[qi], smq + (uint32_t)((32 * w + qi * 16 + (lane & 15)) * 48 +
                                       (lane >> 4) * 16));

    float O0[2][4] = {}, O1[2][4] = {};
    float la[2] = {}, lb[2] = {};

    const int pr = t >> 1, ph2 = t & 1;

    #define KV_PREFETCH(buf, kt) do {                                            \
        const uint32_t sb_ = kvb + (uint32_t)((buf) * KV_STAGE);                  \
        const size_t go_ = gb + (size_t)((kt) + pr) * 16 + ph2 * 8;               \
        const uint32_t so_ = (uint32_t)(pr * 48 + ph2 * 16);                      \
        cp16(sb_ + so_,        g_Kf + go_);                                       \
        cp16(sb_ + 6144 + so_, g_Vf + go_);                                       \
        cp_commit();                                                               \
    } while (0)

    KV_PREFETCH(0, 0);
    KV_PREFETCH(1, 128);

    int cbuf = 0, pbuf = 2;
    for (int s = 0; s < 8; s++) {
        if (s == 7) cp_wait0(); else cp_wait1();
        __syncthreads();
        if (s + 2 < 8) {
            KV_PREFETCH(pbuf, (s + 2) * 128);
            pbuf = (pbuf == 2) ? 0 : pbuf + 1;
        }

        const uint32_t sb = kvb + (uint32_t)(cbuf * KV_STAGE);
        cbuf = (cbuf == 2) ? 0 : cbuf + 1;
        const uint32_t lrow = (uint32_t)((lane & 15) * 48 + (lane >> 4) * 16);

        #pragma unroll
        for (int q4 = 0; q4 < 4; q4++) {
            float S[2][2][2][4];
            #pragma unroll
            for (int a = 0; a < 2; a++)
                #pragma unroll
                for (int b = 0; b < 2; b++)
                    #pragma unroll
                    for (int c = 0; c < 2; c++)
                        #pragma unroll
                        for (int d = 0; d < 4; d++) S[a][b][c][d] = 0.0f;

            #pragma unroll
            for (int kc = 0; kc < 2; kc++) {
                uint32_t kh[4];
                ldsm4(kh, sb + (uint32_t)((q4 * 2 + kc) * 16 * 48) + lrow);
                #pragma unroll
                for (int qi = 0; qi < 2; qi++) {
                    mma_f16(S[kc][qi][0], qf[qi], kh[0], kh[2]);
                    mma_f16(S[kc][qi][1], qf[qi], kh[1], kh[3]);
                }
            }

            #pragma unroll
            for (int kc = 0; kc < 2; kc++) {
                uint32_t pa[2][4];
                #pragma unroll
                for (int qi = 0; qi < 2; qi++) {
                    pa[qi][0] = ex2h2(f2h2(S[kc][qi][0][0], S[kc][qi][0][1]));
                    pa[qi][1] = ex2h2(f2h2(S[kc][qi][0][2], S[kc][qi][0][3]));
                    pa[qi][2] = ex2h2(f2h2(S[kc][qi][1][0], S[kc][qi][1][1]));
                    pa[qi][3] = ex2h2(f2h2(S[kc][qi][1][2], S[kc][qi][1][3]));
                    const float2 fa = __half22float2(__hadd2(u2h(pa[qi][0]), u2h(pa[qi][2])));
                    const float2 fb = __half22float2(__hadd2(u2h(pa[qi][1]), u2h(pa[qi][3])));
                    la[qi] += fa.x + fa.y;
                    lb[qi] += fb.x + fb.y;
                }
                uint32_t vh[4];
                ldsm4t(vh, sb + 6144 + (uint32_t)((q4 * 2 + kc) * 16 * 48) + lrow);
                #pragma unroll
                for (int qi = 0; qi < 2; qi++) {
                    mma_f16(O0[qi], pa[qi], vh[0], vh[1]);
                    mma_f16(O1[qi], pa[qi], vh[2], vh[3]);
                }
            }
        }
    }
    #undef KV_PREFETCH

    const int g = lane >> 2, tq = lane & 3;
    const int b = bh >> 6, hd = bh & 63;
    #pragma unroll
    for (int qi = 0; qi < 2; qi++) {
        float A = la[qi], Bv = lb[qi];
        A  += __shfl_xor_sync(0xFFFFFFFF, A, 1);
        A  += __shfl_xor_sync(0xFFFFFFFF, A, 2);
        Bv += __shfl_xor_sync(0xFFFFFFFF, Bv, 1);
        Bv += __shfl_xor_sync(0xFFFFFFFF, Bv, 2);
        const float ia = 1.0f / A, ib = 1.0f / Bv;

        const int ca = qt + 32 * w + qi * 16 + g, cb = ca + 8;
        const size_t oa = ((size_t)(b * 1024 + ca)) * 1024 + hd * 16 + 2 * tq;
        const size_t ob = ((size_t)(b * 1024 + cb)) * 1024 + hd * 16 + 2 * tq;

        *(uint32_t*)(g_AOf + oa)     = f2h2(O0[qi][0] * ia, O0[qi][1] * ia);
        *(uint32_t*)(g_AOf + oa + 8) = f2h2(O1[qi][0] * ia, O1[qi][1] * ia);
        *(uint32_t*)(g_AOf + ob)     = f2h2(O0[qi][2] * ib, O0[qi][3] * ib);
        *(uint32_t*)(g_AOf + ob + 8) = f2h2(O1[qi][2] * ib, O1[qi][3] * ib);
    }
}

// ---------------------------------------------------------------------------
extern "C" void kernel_launch(void* const* d_in, const int* in_sizes, int n_in,
                              void* d_out, int out_size)
{
    const float* x  = (const float*)d_in[0];
    const float* Wq = (const float*)d_in[1];
    const float* Wk = (const float*)d_in[2];
    const float* Wv = (const float*)d_in[3];
    const float* Wo = (const float*)d_in[4];
    float* out = (float*)d_out;

    cudaFuncSetAttribute(gemm_qkv_k, cudaFuncAttributeMaxDynamicSharedMemorySize, QKV_SMEM);
    cudaFuncSetAttribute(gemm_o_k,   cudaFuncAttributeMaxDynamicSharedMemorySize, O_SMEM);
    cudaFuncSetAttribute(attn_mma_k, cudaFuncAttributeMaxDynamicSharedMemorySize, ATT_SMEM);
    cudaFuncSetAttribute(gemm_qkv_k, cudaFuncAttributePreferredSharedMemoryCarveout, 100);
    cudaFuncSetAttribute(gemm_o_k,   cudaFuncAttributePreferredSharedMemoryCarveout, 100);
    cudaFuncSetAttribute(attn_mma_k, cudaFuncAttributePreferredSharedMemoryCarveout, 100);

    prep_kernel<<<6144, 256>>>((const float4*)x, (const float4*)Wq,
                               (const float4*)Wk, (const float4*)Wv,
                               (const float4*)Wo);

    gemm_qkv_k<<<dim3(8, 16, 3), 256, QKV_SMEM>>>();

    attn_mma_k<<<dim3(4, 128), 256, ATT_SMEM>>>();

    gemm_o_k<<<dim3(16, 16), 256, O_SMEM>>>(out);
}